// round 14
// baseline (speedup 1.0000x reference)
#include <cuda_runtime.h>
#include <cuda_fp16.h>
#include <cstdint>

// Problem dims
#define BB   512
#define NN   512
#define MTOT (BB*NN)      // 262144 rows
#define C1   128
#define C2   256
#define ENC  128
#define EPSV 1e-5f

#define MASK_AT(mk, i) ((mk)[i] != 0)

// ---------------- scratch (activations in f16) ----------------
__device__ half g_h1[(size_t)MTOT * C1];    // h1 pre-BN [BN,128]
__device__ half g_h [(size_t)MTOT * C2];    // masked h  [BN,256]
__device__ half g_h2[(size_t)MTOT * C2];    // h2 (incl pbias) [BN,256]
__device__ float g_pbias[BB * C2];
__device__ float g_stat[768];
__device__ float g_cnt;
__device__ float g_scale1[C1], g_shift1[C1];
__device__ float g_scale2[C2], g_shift2[C2];
__device__ uint32_t g_poolenc[BB * C2];
__device__ uint32_t g_outenc [BB * ENC];
// f16 weights, transposed [n][k]
__device__ half g_w2t[C2 * C1];
__device__ half g_w3t[C2 * C2];
__device__ half g_w4t[ENC * C2];

__device__ __forceinline__ uint32_t smem_u32(const void* p) {
    uint32_t a;
    asm("{ .reg .u64 t; cvta.to.shared.u64 t, %1; cvt.u32.u64 %0, t; }" : "=r"(a) : "l"(p));
    return a;
}
__device__ __forceinline__ void cp_async16_cg(uint32_t dst, const void* src) {
    asm volatile("cp.async.cg.shared.global [%0], [%1], 16;" :: "r"(dst), "l"(src));
}
__device__ __forceinline__ void cp_async16_ca(uint32_t dst, const void* src) {
    asm volatile("cp.async.ca.shared.global [%0], [%1], 16;" :: "r"(dst), "l"(src));
}
#define CP_COMMIT() asm volatile("cp.async.commit_group;" ::: "memory")
#define CP_WAIT0()  asm volatile("cp.async.wait_group 0;" ::: "memory")
#define CP_WAIT1()  asm volatile("cp.async.wait_group 1;" ::: "memory")

__device__ __forceinline__ uint32_t fenc(float f) {
    uint32_t u = __float_as_uint(f);
    return (u >> 31) ? ~u : (u | 0x80000000u);
}
__device__ __forceinline__ float fdec(uint32_t e) {
    return __uint_as_float((e >> 31) ? (e ^ 0x80000000u) : ~e);
}
__device__ __forceinline__ uint32_t packh2(float x, float y) {
    uint32_t r;
    asm("cvt.rn.f16x2.f32 %0, %1, %2;" : "=r"(r) : "f"(y), "f"(x));
    return r;
}
__device__ __forceinline__ half2 u2h(uint32_t u) { return *(half2*)&u; }
__device__ __forceinline__ uint32_t h2u(half2 h) { return *(uint32_t*)&h; }
// packed BN+ReLU: max(a*s + b, 0) in fp16x2
__device__ __forceinline__ uint32_t bnrelu2(uint32_t a, uint32_t s, uint32_t b) {
    half2 z = __float2half2_rn(0.f);
    return h2u(__hmax2(__hfma2(u2h(a), u2h(s), u2h(b)), z));
}

// ---------------- init ----------------
__global__ void init_kernel() {
    int i = blockIdx.x * 256 + threadIdx.x;
    if (i < 768) g_stat[i] = 0.f;
    if (i == 768) g_cnt = 0.f;
    if (i < BB * C2) g_poolenc[i] = 0u;
    if (i < BB * ENC) g_outenc[i] = 0u;
}

// ---------------- weight f16 transpose: Wt[n][k] = h(W[k][n]) ----------------
__global__ void wcvt_t_kernel(const float* __restrict__ W, half* __restrict__ Wt,
                              int K, int N) {
    int i = blockIdx.x * 256 + threadIdx.x;
    if (i >= K * N) return;
    int n = i / K, k = i % K;
    Wt[i] = __float2half_rn(W[(size_t)k * N + n]);
}

// ---------------- K1: h1 = x@W1 + b1 (f16 store), masked BN1 stats (fp32) ----------------
__global__ __launch_bounds__(128) void k1_kernel(const float* __restrict__ x,
                                                 const int* __restrict__ mask,
                                                 const float* __restrict__ W1,
                                                 const float* __restrict__ b1) {
    __shared__ float sW[6 * C1];
    __shared__ float sb[C1];
    int c = threadIdx.x;
#pragma unroll
    for (int k = 0; k < 6; k++) sW[k * C1 + c] = W1[k * C1 + c];
    sb[c] = b1[c];
    __syncthreads();

    int row0 = blockIdx.x * 32;
    float s = 0.f, ss = 0.f;
    int cnt = 0;
    for (int r = 0; r < 32; r++) {
        int row = row0 + r;
        const float* xr = x + (size_t)row * 6;
        float v = sb[c];
#pragma unroll
        for (int k = 0; k < 6; k++) v = fmaf(xr[k], sW[k * C1 + c], v);
        g_h1[(size_t)row * C1 + c] = __float2half_rn(v);
        if (MASK_AT(mask, row)) { s += v; ss += v * v; cnt++; }
    }
    atomicAdd(&g_stat[c],      s);
    atomicAdd(&g_stat[C1 + c], ss);
    if (c == 0) atomicAdd(&g_cnt, (float)cnt);
}

// ---------------- finalize BN ----------------
__global__ void fin1_kernel(const float* __restrict__ g1, const float* __restrict__ be1) {
    int c = threadIdx.x;
    float cnt  = fmaxf(g_cnt, 1.f);
    float mean = g_stat[c] / cnt;
    float var  = g_stat[C1 + c] / cnt - mean * mean;
    float sc   = g1[c] * rsqrtf(var + EPSV);
    g_scale1[c] = sc;
    g_shift1[c] = be1[c] - mean * sc;
}
__global__ void fin2_kernel(const float* __restrict__ g2, const float* __restrict__ be2) {
    int c = threadIdx.x;
    float cnt  = fmaxf(g_cnt, 1.f);
    float mean = g_stat[256 + c] / cnt;
    float var  = g_stat[512 + c] / cnt - mean * mean;
    float sc   = g2[c] * rsqrtf(var + EPSV);
    g_scale2[c] = sc;
    g_shift2[c] = be2[c] - mean * sc;
}

// ================ f16 mma.sync m16n8k16 GEMM, 3-stage cp.async ================
// CTA 128x128 tile, 4 warps (2m x 2n), warp tile 64x64, BK=16. A & B f16 in smem.
// GRID: x = n-tile (fastest), y = row tile (A dup L2-absorbed).
// BN+ReLU applied in packed half2 (HFMA2+HMAX2) on A fragment words.
// MODE 2: A=g_h1 (K=128), BN1+ReLU, bias=b2, mask -> g_h(f16) + poolmax
// MODE 3: A=g_h  (K=256), identity, bias=pbias -> g_h2(f16) + stats
// MODE 4: A=g_h2 (K=256), BN2+ReLU, bias=b4, mask -> final max only
#define PADAH 24   // halfs per A row (16 + 8)
#define PADB  24   // halfs per B row
#define NSTG  3

template <int KDIM, int NDIM, int MODE>
__global__ __launch_bounds__(128, 2) void mma_gemm(const half* __restrict__ Wg,
                                                   const float* __restrict__ biasv,
                                                   const int* __restrict__ mask) {
    constexpr bool BNACT  = (MODE != 3);
    constexpr bool STOREO = (MODE != 4);
    constexpr bool POOLE  = (MODE != 3);
    constexpr bool STATS  = (MODE == 3);
    constexpr int  NKB    = KDIM / 16;
    constexpr int  SCSZ   = BNACT ? KDIM / 2 : 1;   // half2 pairs

    const half* A   = (MODE == 2) ? g_h1 : (MODE == 3) ? g_h : g_h2;
    half*       Out = (MODE == 2) ? g_h  : g_h2;

    __shared__ __align__(16) half As[NSTG][128 * PADAH];
    __shared__ __align__(16) half Bs[NSTG][128 * PADB];
    __shared__ float sBias[128];
    __shared__ uint32_t sScaleH[SCSZ];   // half2(s[2i], s[2i+1])
    __shared__ uint32_t sShiftH[SCSZ];
    __shared__ uint32_t sPool[128];
    __shared__ float sS[128], sSS[128];

    const int t = threadIdx.x;
    const int rowBase = blockIdx.y * 128;   // row tile on y
    const int nBase   = blockIdx.x * 128;   // n tile on x (fastest)
    const int batch   = rowBase >> 9;

    if (t < 128) { sPool[t] = 0u; sS[t] = 0.f; sSS[t] = 0.f; }
    if (MODE == 3) {
        if (t < 128) sBias[t] = g_pbias[batch * C2 + nBase + t];
    } else {
        if (t < 128) sBias[t] = biasv[nBase + t];
        const float* sc = (MODE == 2) ? g_scale1 : g_scale2;
        const float* sh = (MODE == 2) ? g_shift1 : g_shift2;
        for (int i = t; i < KDIM / 2; i += 128) {
            sScaleH[i] = h2u(__floats2half2_rn(sc[2 * i], sc[2 * i + 1]));
            sShiftH[i] = h2u(__floats2half2_rn(sh[2 * i], sh[2 * i + 1]));
        }
    }

    const int w  = t >> 5, l = t & 31;
    const int g  = l >> 2, c = l & 3;
    const int wm = w & 1, wn = w >> 1;
    const int mrow0 = wm * 64;
    const int ncol0 = wn * 64;

    uint32_t asm_base[NSTG], bsm_base[NSTG];
#pragma unroll
    for (int s = 0; s < NSTG; s++) {
        asm_base[s] = smem_u32(&As[s][0]);
        bsm_base[s] = smem_u32(&Bs[s][0]);
    }

    const half* aG = A + (size_t)rowBase * KDIM;
    const half* bG = Wg + (size_t)nBase * KDIM;

    auto issue_tile = [&](int kb, int buf) {
#pragma unroll
        for (int i = 0; i < 2; i++) {
            int f = i * 128 + t;
            int r = f >> 1, hc = f & 1;
            cp_async16_cg(asm_base[buf] + (uint32_t)(r * PADAH + hc * 8) * 2,
                          aG + (size_t)r * KDIM + kb * 16 + hc * 8);
        }
#pragma unroll
        for (int i = 0; i < 2; i++) {
            int f = i * 128 + t;
            int n = f >> 1, hc = f & 1;
            cp_async16_ca(bsm_base[buf] + (uint32_t)(n * PADB + hc * 8) * 2,
                          bG + (size_t)n * KDIM + kb * 16 + hc * 8);
        }
        CP_COMMIT();
    };

    float acc[4][8][4];
#pragma unroll
    for (int mt = 0; mt < 4; mt++)
#pragma unroll
        for (int nt = 0; nt < 8; nt++)
#pragma unroll
            for (int q = 0; q < 4; q++) acc[mt][nt][q] = 0.f;

    issue_tile(0, 0);
    issue_tile(1, 1);

#pragma unroll 1
    for (int kb = 0; kb < NKB; kb++) {
        const int buf = kb % NSTG;
        if (kb + 1 < NKB) { CP_WAIT1(); } else { CP_WAIT0(); }
        __syncthreads();
        if (kb + 2 < NKB) issue_tile(kb + 2, (kb + 2) % NSTG);

        // packed BN params: k pair index kb*8 + c (k = kb*16 + 2c,2c+1)
        //                   and kb*8 + 4 + c  (k = kb*16 + 8 + 2c, +1)
        uint32_t sc01 = 0, sh01 = 0, sc89 = 0, sh89 = 0;
        if (BNACT) {
            sc01 = sScaleH[kb * 8 + c];     sh01 = sShiftH[kb * 8 + c];
            sc89 = sScaleH[kb * 8 + 4 + c]; sh89 = sShiftH[kb * 8 + 4 + c];
        }

        uint32_t afr[4][4];
#pragma unroll
        for (int mt = 0; mt < 4; mt++) {
            const half* ap = &As[buf][(mrow0 + mt * 16 + g) * PADAH];
            uint32_t w0 = *(const uint32_t*)(ap + 2 * c);
            uint32_t w1 = *(const uint32_t*)(ap + 8 * PADAH + 2 * c);
            uint32_t w2 = *(const uint32_t*)(ap + 2 * c + 8);
            uint32_t w3 = *(const uint32_t*)(ap + 8 * PADAH + 2 * c + 8);
            if (BNACT) {
                w0 = bnrelu2(w0, sc01, sh01);
                w1 = bnrelu2(w1, sc01, sh01);
                w2 = bnrelu2(w2, sc89, sh89);
                w3 = bnrelu2(w3, sc89, sh89);
            }
            afr[mt][0] = w0; afr[mt][1] = w1; afr[mt][2] = w2; afr[mt][3] = w3;
        }
#pragma unroll
        for (int nt = 0; nt < 8; nt++) {
            const half* bp = &Bs[buf][(ncol0 + nt * 8 + g) * PADB];
            uint32_t b0 = *(const uint32_t*)(bp + 2 * c);
            uint32_t b1 = *(const uint32_t*)(bp + 2 * c + 8);
#pragma unroll
            for (int mt = 0; mt < 4; mt++) {
                asm volatile(
                    "mma.sync.aligned.m16n8k16.row.col.f32.f16.f16.f32 "
                    "{%0,%1,%2,%3}, {%4,%5,%6,%7}, {%8,%9}, {%0,%1,%2,%3};"
                    : "+f"(acc[mt][nt][0]), "+f"(acc[mt][nt][1]),
                      "+f"(acc[mt][nt][2]), "+f"(acc[mt][nt][3])
                    : "r"(afr[mt][0]), "r"(afr[mt][1]),
                      "r"(afr[mt][2]), "r"(afr[mt][3]),
                      "r"(b0), "r"(b1));
            }
        }
        __syncthreads();
    }

    // ---- epilogue: f16 store + fused reductions ----
    float lmax[8][2];
    float stS[8][2], stSS[8][2];
    if (POOLE) {
#pragma unroll
        for (int nt = 0; nt < 8; nt++) { lmax[nt][0] = -3.4e38f; lmax[nt][1] = -3.4e38f; }
    }
    if (STATS) {
#pragma unroll
        for (int nt = 0; nt < 8; nt++) {
            stS[nt][0] = 0.f; stS[nt][1] = 0.f; stSS[nt][0] = 0.f; stSS[nt][1] = 0.f;
        }
    }

#pragma unroll
    for (int mt = 0; mt < 4; mt++) {
        int r0 = rowBase + mrow0 + mt * 16 + g;
        int r1 = r0 + 8;
        float m0 = MASK_AT(mask, r0) ? 1.f : 0.f;
        float m1 = MASK_AT(mask, r1) ? 1.f : 0.f;
        half* o0 = Out + (size_t)r0 * NDIM + nBase;
        half* o1 = Out + (size_t)r1 * NDIM + nBase;
#pragma unroll
        for (int nt = 0; nt < 8; nt++) {
            int col = ncol0 + nt * 8 + 2 * c;
            float bx = sBias[col], by = sBias[col + 1];
            float ux = acc[mt][nt][0] + bx, uy = acc[mt][nt][1] + by;
            float vx = acc[mt][nt][2] + bx, vy = acc[mt][nt][3] + by;
            if (MODE != 3) { ux *= m0; uy *= m0; vx *= m1; vy *= m1; }
            if (STOREO) {
                *(uint32_t*)(o0 + col) = packh2(ux, uy);
                *(uint32_t*)(o1 + col) = packh2(vx, vy);
            }
            if (POOLE) {
                lmax[nt][0] = fmaxf(lmax[nt][0], fmaxf(ux, vx));
                lmax[nt][1] = fmaxf(lmax[nt][1], fmaxf(uy, vy));
            }
            if (STATS) {
                stS[nt][0]  += m0 * ux + m1 * vx;
                stS[nt][1]  += m0 * uy + m1 * vy;
                stSS[nt][0] += m0 * ux * ux + m1 * vx * vx;
                stSS[nt][1] += m0 * uy * uy + m1 * vy * vy;
            }
        }
    }

    if (POOLE) {
#pragma unroll
        for (int nt = 0; nt < 8; nt++) {
            atomicMax(&sPool[ncol0 + nt * 8 + 2 * c],     fenc(lmax[nt][0]));
            atomicMax(&sPool[ncol0 + nt * 8 + 2 * c + 1], fenc(lmax[nt][1]));
        }
    }
    if (STATS) {
#pragma unroll
        for (int nt = 0; nt < 8; nt++) {
            int col = ncol0 + nt * 8 + 2 * c;
            atomicAdd(&sS[col],      stS[nt][0]);
            atomicAdd(&sS[col + 1],  stS[nt][1]);
            atomicAdd(&sSS[col],     stSS[nt][0]);
            atomicAdd(&sSS[col + 1], stSS[nt][1]);
        }
    }
    __syncthreads();
    if (t < 128) {
        if (MODE == 2) atomicMax(&g_poolenc[batch * C2 + nBase + t], sPool[t]);
        if (MODE == 4) atomicMax(&g_outenc[batch * ENC + t], sPool[t]);
        if (STATS) {
            atomicAdd(&g_stat[256 + nBase + t], sS[t]);
            atomicAdd(&g_stat[512 + nBase + t], sSS[t]);
        }
    }
}

// ---------------- pbias = pooled @ W3[256:512] + b3 ----------------
__global__ void pbias_kernel(const float* __restrict__ W3, const float* __restrict__ b3) {
    __shared__ float sp[C2];
    int b = blockIdx.x, c = threadIdx.x;  // 256
    sp[c] = fdec(g_poolenc[b * C2 + c]);
    __syncthreads();
    float v = b3[c];
    for (int k = 0; k < C2; k++) v = fmaf(sp[k], W3[(size_t)(C2 + k) * C2 + c], v);
    g_pbias[b * C2 + c] = v;
}

// ---------------- decode final output ----------------
__global__ void decode_out_kernel(float* __restrict__ out) {
    int i = blockIdx.x * 256 + threadIdx.x;
    if (i < BB * ENC) out[i] = fdec(g_outenc[i]);
}

// ---------------- launch ----------------
extern "C" void kernel_launch(void* const* d_in, const int* in_sizes, int n_in,
                              void* d_out, int out_size) {
    const float* x  = (const float*)d_in[0];
    const int*   mk = (const int*)d_in[1];
    const float* W1 = (const float*)d_in[2];
    const float* b1 = (const float*)d_in[3];
    const float* g1 = (const float*)d_in[4];
    const float* be1= (const float*)d_in[5];
    const float* W2 = (const float*)d_in[6];
    const float* b2 = (const float*)d_in[7];
    const float* W3 = (const float*)d_in[8];
    const float* b3 = (const float*)d_in[9];
    const float* g2 = (const float*)d_in[10];
    const float* be2= (const float*)d_in[11];
    const float* W4 = (const float*)d_in[12];
    const float* b4 = (const float*)d_in[13];
    float* out = (float*)d_out;

    half *w2t, *w3t, *w4t;
    cudaGetSymbolAddress((void**)&w2t, g_w2t);
    cudaGetSymbolAddress((void**)&w3t, g_w3t);
    cudaGetSymbolAddress((void**)&w4t, g_w4t);

    init_kernel<<<(BB * C2 + 255) / 256, 256>>>();
    wcvt_t_kernel<<<(C1 * C2 + 255) / 256, 256>>>(W2, w2t, C1, C2);
    wcvt_t_kernel<<<(C2 * C2 + 255) / 256, 256>>>(W3, w3t, C2, C2);  // rows 0..255 of W3
    wcvt_t_kernel<<<(C2 * ENC + 255) / 256, 256>>>(W4, w4t, C2, ENC);

    k1_kernel<<<MTOT / 32, 128>>>(x, mk, W1, b1);
    fin1_kernel<<<1, 128>>>(g1, be1);

    // grid: x = n-tiles (fastest), y = row tiles -> n-halves co-resident, A L2-absorbed
    mma_gemm<128, 256, 2><<<dim3(2, MTOT / 128), 128>>>(w2t, b2, mk);
    pbias_kernel<<<BB, 256>>>(W3, b3);
    mma_gemm<256, 256, 3><<<dim3(2, MTOT / 128), 128>>>(w3t, nullptr, mk);
    fin2_kernel<<<1, 256>>>(g2, be2);
    mma_gemm<256, 128, 4><<<dim3(1, MTOT / 128), 128>>>(w4t, b4, mk);
    decode_out_kernel<<<(BB * ENC + 255) / 256, 256>>>(out);
}

// round 15
// speedup vs baseline: 1.5852x; 1.5852x over previous
#include <cuda_runtime.h>
#include <cuda_fp16.h>
#include <cstdint>

// Problem dims
#define BB   512
#define NN   512
#define MTOT (BB*NN)      // 262144 rows
#define C1   128
#define C2   256
#define ENC  128
#define EPSV 1e-5f

#define MASK_AT(mk, i) ((mk)[i] != 0)

// ---------------- scratch (activations in f16) ----------------
__device__ half g_h1[(size_t)MTOT * C1];    // h1 pre-BN [BN,128]
__device__ half g_h [(size_t)MTOT * C2];    // masked h  [BN,256]
__device__ half g_h2[(size_t)MTOT * C2];    // h2 (incl pbias) [BN,256]
__device__ float g_pbias[BB * C2];
__device__ float g_stat[768];
__device__ float g_cnt;
__device__ float g_scale1[C1], g_shift1[C1];
__device__ float g_scale2[C2], g_shift2[C2];
__device__ uint32_t g_poolenc[BB * C2];
__device__ uint32_t g_outenc [BB * ENC];
// f16 weights, transposed [n][k]
__device__ half g_w2t[C2 * C1];
__device__ half g_w3t[C2 * C2];
__device__ half g_w4t[ENC * C2];

__device__ __forceinline__ uint32_t smem_u32(const void* p) {
    uint32_t a;
    asm("{ .reg .u64 t; cvta.to.shared.u64 t, %1; cvt.u32.u64 %0, t; }" : "=r"(a) : "l"(p));
    return a;
}
__device__ __forceinline__ void cp_async16_cg(uint32_t dst, const void* src) {
    asm volatile("cp.async.cg.shared.global [%0], [%1], 16;" :: "r"(dst), "l"(src));
}
__device__ __forceinline__ void cp_async16_ca(uint32_t dst, const void* src) {
    asm volatile("cp.async.ca.shared.global [%0], [%1], 16;" :: "r"(dst), "l"(src));
}
#define CP_COMMIT() asm volatile("cp.async.commit_group;" ::: "memory")
#define CP_WAIT0()  asm volatile("cp.async.wait_group 0;" ::: "memory")
#define CP_WAIT1()  asm volatile("cp.async.wait_group 1;" ::: "memory")

__device__ __forceinline__ uint32_t fenc(float f) {
    uint32_t u = __float_as_uint(f);
    return (u >> 31) ? ~u : (u | 0x80000000u);
}
__device__ __forceinline__ float fdec(uint32_t e) {
    return __uint_as_float((e >> 31) ? (e ^ 0x80000000u) : ~e);
}
__device__ __forceinline__ uint32_t packh2(float x, float y) {
    uint32_t r;
    asm("cvt.rn.f16x2.f32 %0, %1, %2;" : "=r"(r) : "f"(y), "f"(x));
    return r;
}
__device__ __forceinline__ float2 uph2(uint32_t u) {
    half2 h = *(half2*)&u;
    return __half22float2(h);
}

// ---------------- init ----------------
__global__ void init_kernel() {
    int i = blockIdx.x * 256 + threadIdx.x;
    if (i < 768) g_stat[i] = 0.f;
    if (i == 768) g_cnt = 0.f;
    if (i < BB * C2) g_poolenc[i] = 0u;
    if (i < BB * ENC) g_outenc[i] = 0u;
}

// ---------------- weight f16 transpose: Wt[n][k] = h(W[k][n]) ----------------
__global__ void wcvt_t_kernel(const float* __restrict__ W, half* __restrict__ Wt,
                              int K, int N) {
    int i = blockIdx.x * 256 + threadIdx.x;
    if (i >= K * N) return;
    int n = i / K, k = i % K;
    Wt[i] = __float2half_rn(W[(size_t)k * N + n]);
}

// ---------------- K1: h1 = x@W1 + b1 (f16 store), masked BN1 stats (fp32) ----------------
__global__ __launch_bounds__(128) void k1_kernel(const float* __restrict__ x,
                                                 const int* __restrict__ mask,
                                                 const float* __restrict__ W1,
                                                 const float* __restrict__ b1) {
    __shared__ float sW[6 * C1];
    __shared__ float sb[C1];
    int c = threadIdx.x;
#pragma unroll
    for (int k = 0; k < 6; k++) sW[k * C1 + c] = W1[k * C1 + c];
    sb[c] = b1[c];
    __syncthreads();

    int row0 = blockIdx.x * 32;
    float s = 0.f, ss = 0.f;
    int cnt = 0;
    for (int r = 0; r < 32; r++) {
        int row = row0 + r;
        const float* xr = x + (size_t)row * 6;
        float v = sb[c];
#pragma unroll
        for (int k = 0; k < 6; k++) v = fmaf(xr[k], sW[k * C1 + c], v);
        g_h1[(size_t)row * C1 + c] = __float2half_rn(v);
        if (MASK_AT(mask, row)) { s += v; ss += v * v; cnt++; }
    }
    atomicAdd(&g_stat[c],      s);
    atomicAdd(&g_stat[C1 + c], ss);
    if (c == 0) atomicAdd(&g_cnt, (float)cnt);
}

// ---------------- finalize BN ----------------
__global__ void fin1_kernel(const float* __restrict__ g1, const float* __restrict__ be1) {
    int c = threadIdx.x;
    float cnt  = fmaxf(g_cnt, 1.f);
    float mean = g_stat[c] / cnt;
    float var  = g_stat[C1 + c] / cnt - mean * mean;
    float sc   = g1[c] * rsqrtf(var + EPSV);
    g_scale1[c] = sc;
    g_shift1[c] = be1[c] - mean * sc;
}
__global__ void fin2_kernel(const float* __restrict__ g2, const float* __restrict__ be2) {
    int c = threadIdx.x;
    float cnt  = fmaxf(g_cnt, 1.f);
    float mean = g_stat[256 + c] / cnt;
    float var  = g_stat[512 + c] / cnt - mean * mean;
    float sc   = g2[c] * rsqrtf(var + EPSV);
    g_scale2[c] = sc;
    g_shift2[c] = be2[c] - mean * sc;
}

// ================ f16 mma.sync m16n8k16 GEMM, 3-stage cp.async, BK=32 =========
// CTA 128x128 tile, 4 warps (2m x 2n), warp tile 64x64. Stage = 32 k-halfs
// (two 16-wide mma sub-steps per buffer) -> half the barriers of BK=16.
// GRID: x = n-tile (fastest), y = row tile (A dup L2-absorbed).
// MODE 2: A=g_h1 (K=128), BN1+ReLU fp32 at frag, bias=b2, mask -> g_h + poolmax
// MODE 3: A=g_h  (K=256), identity, bias=pbias -> g_h2 + stats
// MODE 4: A=g_h2 (K=256), BN2+ReLU fp32 at frag, bias=b4, mask -> final max only
#define PAD32 40       // halfs per row (32 + 8); 20-word stride, conflict-free
#define STAGE_BYTES 10240   // 128 * 40 * 2
#define NSTG  3
#define DYN_TOTAL (NSTG * STAGE_BYTES * 2)   // 61440

template <int KDIM, int NDIM, int MODE>
__global__ __launch_bounds__(128, 2) void mma_gemm(const half* __restrict__ Wg,
                                                   const float* __restrict__ biasv,
                                                   const int* __restrict__ mask) {
    constexpr bool BNACT  = (MODE != 3);
    constexpr bool STOREO = (MODE != 4);
    constexpr bool POOLE  = (MODE != 3);
    constexpr bool STATS  = (MODE == 3);
    constexpr int  NKB    = KDIM / 32;
    constexpr int  SCSZ   = BNACT ? KDIM : 1;

    const half* A   = (MODE == 2) ? g_h1 : (MODE == 3) ? g_h : g_h2;
    half*       Out = (MODE == 2) ? g_h  : g_h2;

    extern __shared__ char dyn[];
    __shared__ float sBias[128];
    __shared__ float sScale[SCSZ];
    __shared__ float sShift[SCSZ];
    __shared__ uint32_t sPool[128];
    __shared__ float sS[128], sSS[128];

    const int t = threadIdx.x;
    const int rowBase = blockIdx.y * 128;   // row tile on y
    const int nBase   = blockIdx.x * 128;   // n tile on x (fastest)
    const int batch   = rowBase >> 9;

    if (t < 128) { sPool[t] = 0u; sS[t] = 0.f; sSS[t] = 0.f; }
    if (MODE == 3) {
        if (t < 128) sBias[t] = g_pbias[batch * C2 + nBase + t];
    } else {
        if (t < 128) sBias[t] = biasv[nBase + t];
        const float* sc = (MODE == 2) ? g_scale1 : g_scale2;
        const float* sh = (MODE == 2) ? g_shift1 : g_shift2;
        for (int r = t; r < KDIM; r += 128) { sScale[r] = sc[r]; sShift[r] = sh[r]; }
    }

    const int w  = t >> 5, l = t & 31;
    const int g  = l >> 2, c = l & 3;
    const int wm = w & 1, wn = w >> 1;
    const int mrow0 = wm * 64;
    const int ncol0 = wn * 64;

    uint32_t asm_base[NSTG], bsm_base[NSTG];
#pragma unroll
    for (int s = 0; s < NSTG; s++) {
        asm_base[s] = smem_u32(dyn + s * STAGE_BYTES);
        bsm_base[s] = smem_u32(dyn + NSTG * STAGE_BYTES + s * STAGE_BYTES);
    }

    const half* aG = A + (size_t)rowBase * KDIM;
    const half* bG = Wg + (size_t)nBase * KDIM;

    // Per stage: 128 rows x 32 halfs = 64B/row = 512 x 16B chunks; 4/thread each A,B
    auto issue_tile = [&](int kb, int buf) {
#pragma unroll
        for (int i = 0; i < 4; i++) {
            int f = i * 128 + t;
            int r = f >> 2, hc = f & 3;
            cp_async16_cg(asm_base[buf] + (uint32_t)r * 80 + (uint32_t)hc * 16,
                          aG + (size_t)r * KDIM + kb * 32 + hc * 8);
        }
#pragma unroll
        for (int i = 0; i < 4; i++) {
            int f = i * 128 + t;
            int n = f >> 2, hc = f & 3;
            cp_async16_ca(bsm_base[buf] + (uint32_t)n * 80 + (uint32_t)hc * 16,
                          bG + (size_t)n * KDIM + kb * 32 + hc * 8);
        }
        CP_COMMIT();
    };

    float acc[4][8][4];
#pragma unroll
    for (int mt = 0; mt < 4; mt++)
#pragma unroll
        for (int nt = 0; nt < 8; nt++)
#pragma unroll
            for (int q = 0; q < 4; q++) acc[mt][nt][q] = 0.f;

    issue_tile(0, 0);
    issue_tile(1, 1);

#pragma unroll 1
    for (int kb = 0; kb < NKB; kb++) {
        const int buf = kb % NSTG;
        if (kb + 1 < NKB) { CP_WAIT1(); } else { CP_WAIT0(); }
        __syncthreads();
        if (kb + 2 < NKB) issue_tile(kb + 2, (kb + 2) % NSTG);

        const half* AsBuf = (const half*)(dyn + buf * STAGE_BYTES);
        const half* BsBuf = (const half*)(dyn + NSTG * STAGE_BYTES + buf * STAGE_BYTES);

#pragma unroll
        for (int ks = 0; ks < 2; ks++) {
            float s0 = 1.f, s1 = 1.f, s2 = 1.f, s3 = 1.f;
            float h0 = 0.f, h1v = 0.f, h2v = 0.f, h3 = 0.f;
            if (BNACT) {
                int k0 = kb * 32 + ks * 16 + 2 * c;
                s0 = sScale[k0];     h0  = sShift[k0];
                s1 = sScale[k0 + 1]; h1v = sShift[k0 + 1];
                s2 = sScale[k0 + 8]; h2v = sShift[k0 + 8];
                s3 = sScale[k0 + 9]; h3  = sShift[k0 + 9];
            }

            uint32_t afr[4][4];
#pragma unroll
            for (int mt = 0; mt < 4; mt++) {
                const half* ap = &AsBuf[(mrow0 + mt * 16 + g) * PAD32 + ks * 16];
                uint32_t w0 = *(const uint32_t*)(ap + 2 * c);
                uint32_t w1 = *(const uint32_t*)(ap + 8 * PAD32 + 2 * c);
                uint32_t w2 = *(const uint32_t*)(ap + 2 * c + 8);
                uint32_t w3 = *(const uint32_t*)(ap + 8 * PAD32 + 2 * c + 8);
                if (BNACT) {
                    float2 u0 = uph2(w0), u1 = uph2(w1), u2 = uph2(w2), u3 = uph2(w3);
                    u0.x = fmaxf(fmaf(u0.x, s0, h0), 0.f);  u0.y = fmaxf(fmaf(u0.y, s1, h1v), 0.f);
                    u1.x = fmaxf(fmaf(u1.x, s0, h0), 0.f);  u1.y = fmaxf(fmaf(u1.y, s1, h1v), 0.f);
                    u2.x = fmaxf(fmaf(u2.x, s2, h2v), 0.f); u2.y = fmaxf(fmaf(u2.y, s3, h3), 0.f);
                    u3.x = fmaxf(fmaf(u3.x, s2, h2v), 0.f); u3.y = fmaxf(fmaf(u3.y, s3, h3), 0.f);
                    w0 = packh2(u0.x, u0.y);
                    w1 = packh2(u1.x, u1.y);
                    w2 = packh2(u2.x, u2.y);
                    w3 = packh2(u3.x, u3.y);
                }
                afr[mt][0] = w0; afr[mt][1] = w1; afr[mt][2] = w2; afr[mt][3] = w3;
            }
#pragma unroll
            for (int nt = 0; nt < 8; nt++) {
                const half* bp = &BsBuf[(ncol0 + nt * 8 + g) * PAD32 + ks * 16];
                uint32_t b0 = *(const uint32_t*)(bp + 2 * c);
                uint32_t b1 = *(const uint32_t*)(bp + 2 * c + 8);
#pragma unroll
                for (int mt = 0; mt < 4; mt++) {
                    asm volatile(
                        "mma.sync.aligned.m16n8k16.row.col.f32.f16.f16.f32 "
                        "{%0,%1,%2,%3}, {%4,%5,%6,%7}, {%8,%9}, {%0,%1,%2,%3};"
                        : "+f"(acc[mt][nt][0]), "+f"(acc[mt][nt][1]),
                          "+f"(acc[mt][nt][2]), "+f"(acc[mt][nt][3])
                        : "r"(afr[mt][0]), "r"(afr[mt][1]),
                          "r"(afr[mt][2]), "r"(afr[mt][3]),
                          "r"(b0), "r"(b1));
                }
            }
        }
        __syncthreads();
    }

    // ---- epilogue: f16 store + fused reductions ----
    float lmax[8][2];
    float stS[8][2], stSS[8][2];
    if (POOLE) {
#pragma unroll
        for (int nt = 0; nt < 8; nt++) { lmax[nt][0] = -3.4e38f; lmax[nt][1] = -3.4e38f; }
    }
    if (STATS) {
#pragma unroll
        for (int nt = 0; nt < 8; nt++) {
            stS[nt][0] = 0.f; stS[nt][1] = 0.f; stSS[nt][0] = 0.f; stSS[nt][1] = 0.f;
        }
    }

#pragma unroll
    for (int mt = 0; mt < 4; mt++) {
        int r0 = rowBase + mrow0 + mt * 16 + g;
        int r1 = r0 + 8;
        float m0 = MASK_AT(mask, r0) ? 1.f : 0.f;
        float m1 = MASK_AT(mask, r1) ? 1.f : 0.f;
        half* o0 = Out + (size_t)r0 * NDIM + nBase;
        half* o1 = Out + (size_t)r1 * NDIM + nBase;
#pragma unroll
        for (int nt = 0; nt < 8; nt++) {
            int col = ncol0 + nt * 8 + 2 * c;
            float bx = sBias[col], by = sBias[col + 1];
            float ux = acc[mt][nt][0] + bx, uy = acc[mt][nt][1] + by;
            float vx = acc[mt][nt][2] + bx, vy = acc[mt][nt][3] + by;
            if (MODE != 3) { ux *= m0; uy *= m0; vx *= m1; vy *= m1; }
            if (STOREO) {
                *(uint32_t*)(o0 + col) = packh2(ux, uy);
                *(uint32_t*)(o1 + col) = packh2(vx, vy);
            }
            if (POOLE) {
                lmax[nt][0] = fmaxf(lmax[nt][0], fmaxf(ux, vx));
                lmax[nt][1] = fmaxf(lmax[nt][1], fmaxf(uy, vy));
            }
            if (STATS) {
                stS[nt][0]  += m0 * ux + m1 * vx;
                stS[nt][1]  += m0 * uy + m1 * vy;
                stSS[nt][0] += m0 * ux * ux + m1 * vx * vx;
                stSS[nt][1] += m0 * uy * uy + m1 * vy * vy;
            }
        }
    }

    if (POOLE) {
#pragma unroll
        for (int nt = 0; nt < 8; nt++) {
            atomicMax(&sPool[ncol0 + nt * 8 + 2 * c],     fenc(lmax[nt][0]));
            atomicMax(&sPool[ncol0 + nt * 8 + 2 * c + 1], fenc(lmax[nt][1]));
        }
    }
    if (STATS) {
#pragma unroll
        for (int nt = 0; nt < 8; nt++) {
            int col = ncol0 + nt * 8 + 2 * c;
            atomicAdd(&sS[col],      stS[nt][0]);
            atomicAdd(&sS[col + 1],  stS[nt][1]);
            atomicAdd(&sSS[col],     stSS[nt][0]);
            atomicAdd(&sSS[col + 1], stSS[nt][1]);
        }
    }
    __syncthreads();
    if (t < 128) {
        if (MODE == 2) atomicMax(&g_poolenc[batch * C2 + nBase + t], sPool[t]);
        if (MODE == 4) atomicMax(&g_outenc[batch * ENC + t], sPool[t]);
        if (STATS) {
            atomicAdd(&g_stat[256 + nBase + t], sS[t]);
            atomicAdd(&g_stat[512 + nBase + t], sSS[t]);
        }
    }
}

// ---------------- pbias = pooled @ W3[256:512] + b3 ----------------
__global__ void pbias_kernel(const float* __restrict__ W3, const float* __restrict__ b3) {
    __shared__ float sp[C2];
    int b = blockIdx.x, c = threadIdx.x;  // 256
    sp[c] = fdec(g_poolenc[b * C2 + c]);
    __syncthreads();
    float v = b3[c];
    for (int k = 0; k < C2; k++) v = fmaf(sp[k], W3[(size_t)(C2 + k) * C2 + c], v);
    g_pbias[b * C2 + c] = v;
}

// ---------------- decode final output ----------------
__global__ void decode_out_kernel(float* __restrict__ out) {
    int i = blockIdx.x * 256 + threadIdx.x;
    if (i < BB * ENC) out[i] = fdec(g_outenc[i]);
}

// ---------------- launch ----------------
extern "C" void kernel_launch(void* const* d_in, const int* in_sizes, int n_in,
                              void* d_out, int out_size) {
    const float* x  = (const float*)d_in[0];
    const int*   mk = (const int*)d_in[1];
    const float* W1 = (const float*)d_in[2];
    const float* b1 = (const float*)d_in[3];
    const float* g1 = (const float*)d_in[4];
    const float* be1= (const float*)d_in[5];
    const float* W2 = (const float*)d_in[6];
    const float* b2 = (const float*)d_in[7];
    const float* W3 = (const float*)d_in[8];
    const float* b3 = (const float*)d_in[9];
    const float* g2 = (const float*)d_in[10];
    const float* be2= (const float*)d_in[11];
    const float* W4 = (const float*)d_in[12];
    const float* b4 = (const float*)d_in[13];
    float* out = (float*)d_out;

    half *w2t, *w3t, *w4t;
    cudaGetSymbolAddress((void**)&w2t, g_w2t);
    cudaGetSymbolAddress((void**)&w3t, g_w3t);
    cudaGetSymbolAddress((void**)&w4t, g_w4t);

    static bool attr_done = false;
    if (!attr_done) {
        cudaFuncSetAttribute(mma_gemm<128, 256, 2>, cudaFuncAttributeMaxDynamicSharedMemorySize, DYN_TOTAL);
        cudaFuncSetAttribute(mma_gemm<256, 256, 3>, cudaFuncAttributeMaxDynamicSharedMemorySize, DYN_TOTAL);
        cudaFuncSetAttribute(mma_gemm<256, 128, 4>, cudaFuncAttributeMaxDynamicSharedMemorySize, DYN_TOTAL);
        attr_done = true;
    }

    init_kernel<<<(BB * C2 + 255) / 256, 256>>>();
    wcvt_t_kernel<<<(C1 * C2 + 255) / 256, 256>>>(W2, w2t, C1, C2);
    wcvt_t_kernel<<<(C2 * C2 + 255) / 256, 256>>>(W3, w3t, C2, C2);  // rows 0..255 of W3
    wcvt_t_kernel<<<(C2 * ENC + 255) / 256, 256>>>(W4, w4t, C2, ENC);

    k1_kernel<<<MTOT / 32, 128>>>(x, mk, W1, b1);
    fin1_kernel<<<1, 128>>>(g1, be1);

    // grid: x = n-tiles (fastest), y = row tiles -> n-halves co-resident, A L2-absorbed
    mma_gemm<128, 256, 2><<<dim3(2, MTOT / 128), 128, DYN_TOTAL>>>(w2t, b2, mk);
    pbias_kernel<<<BB, 256>>>(W3, b3);
    mma_gemm<256, 256, 3><<<dim3(2, MTOT / 128), 128, DYN_TOTAL>>>(w3t, nullptr, mk);
    fin2_kernel<<<1, 256>>>(g2, be2);
    mma_gemm<256, 128, 4><<<dim3(1, MTOT / 128), 128, DYN_TOTAL>>>(w4t, b4, mk);
    decode_out_kernel<<<(BB * ENC + 255) / 256, 256>>>(out);
}

// round 16
// speedup vs baseline: 1.5919x; 1.0042x over previous
#include <cuda_runtime.h>
#include <cuda_fp16.h>
#include <cstdint>

// Problem dims
#define BB   512
#define NN   512
#define MTOT (BB*NN)      // 262144 rows
#define C1   128
#define C2   256
#define ENC  128
#define EPSV 1e-5f

#define MASK_AT(mk, i) ((mk)[i] != 0)

// ---------------- scratch (activations in f16) ----------------
__device__ half g_h1[(size_t)MTOT * C1];    // h1 pre-BN [BN,128]
__device__ half g_h [(size_t)MTOT * C2];    // masked h  [BN,256]
__device__ half g_h2[(size_t)MTOT * C2];    // h2 (incl pbias) [BN,256]
__device__ float g_pbias[BB * C2];
__device__ float g_stat[768];
__device__ float g_cnt;
__device__ float g_scale1[C1], g_shift1[C1];
__device__ float g_scale2[C2], g_shift2[C2];
__device__ uint32_t g_poolenc[BB * C2];
__device__ uint32_t g_outenc [BB * ENC];
// f16 weights, transposed [n][k]
__device__ half g_w2t[C2 * C1];
__device__ half g_w3t[C2 * C2];
__device__ half g_w4t[ENC * C2];

__device__ __forceinline__ uint32_t smem_u32(const void* p) {
    uint32_t a;
    asm("{ .reg .u64 t; cvta.to.shared.u64 t, %1; cvt.u32.u64 %0, t; }" : "=r"(a) : "l"(p));
    return a;
}
__device__ __forceinline__ void cp_async16_cg(uint32_t dst, const void* src) {
    asm volatile("cp.async.cg.shared.global [%0], [%1], 16;" :: "r"(dst), "l"(src));
}
__device__ __forceinline__ void cp_async16_ca(uint32_t dst, const void* src) {
    asm volatile("cp.async.ca.shared.global [%0], [%1], 16;" :: "r"(dst), "l"(src));
}
#define CP_COMMIT() asm volatile("cp.async.commit_group;" ::: "memory")
#define CP_WAIT0()  asm volatile("cp.async.wait_group 0;" ::: "memory")
#define CP_WAIT1()  asm volatile("cp.async.wait_group 1;" ::: "memory")
#define CP_WAIT2()  asm volatile("cp.async.wait_group 2;" ::: "memory")

__device__ __forceinline__ uint32_t fenc(float f) {
    uint32_t u = __float_as_uint(f);
    return (u >> 31) ? ~u : (u | 0x80000000u);
}
__device__ __forceinline__ float fdec(uint32_t e) {
    return __uint_as_float((e >> 31) ? (e ^ 0x80000000u) : ~e);
}
__device__ __forceinline__ uint32_t packh2(float x, float y) {
    uint32_t r;
    asm("cvt.rn.f16x2.f32 %0, %1, %2;" : "=r"(r) : "f"(y), "f"(x));
    return r;
}
__device__ __forceinline__ float2 uph2(uint32_t u) {
    half2 h = *(half2*)&u;
    return __half22float2(h);
}

// ---------------- init ----------------
__global__ void init_kernel() {
    int i = blockIdx.x * 256 + threadIdx.x;
    if (i < 768) g_stat[i] = 0.f;
    if (i == 768) g_cnt = 0.f;
    if (i < BB * C2) g_poolenc[i] = 0u;
    if (i < BB * ENC) g_outenc[i] = 0u;
}

// ---------------- weight f16 transpose: Wt[n][k] = h(W[k][n]) ----------------
__global__ void wcvt_t_kernel(const float* __restrict__ W, half* __restrict__ Wt,
                              int K, int N) {
    int i = blockIdx.x * 256 + threadIdx.x;
    if (i >= K * N) return;
    int n = i / K, k = i % K;
    Wt[i] = __float2half_rn(W[(size_t)k * N + n]);
}

// ---------------- K1: h1 = x@W1 + b1 (f16 store), masked BN1 stats (fp32) ----------------
__global__ __launch_bounds__(128) void k1_kernel(const float* __restrict__ x,
                                                 const int* __restrict__ mask,
                                                 const float* __restrict__ W1,
                                                 const float* __restrict__ b1) {
    __shared__ float sW[6 * C1];
    __shared__ float sb[C1];
    int c = threadIdx.x;
#pragma unroll
    for (int k = 0; k < 6; k++) sW[k * C1 + c] = W1[k * C1 + c];
    sb[c] = b1[c];
    __syncthreads();

    int row0 = blockIdx.x * 32;
    float s = 0.f, ss = 0.f;
    int cnt = 0;
    for (int r = 0; r < 32; r++) {
        int row = row0 + r;
        const float* xr = x + (size_t)row * 6;
        float v = sb[c];
#pragma unroll
        for (int k = 0; k < 6; k++) v = fmaf(xr[k], sW[k * C1 + c], v);
        g_h1[(size_t)row * C1 + c] = __float2half_rn(v);
        if (MASK_AT(mask, row)) { s += v; ss += v * v; cnt++; }
    }
    atomicAdd(&g_stat[c],      s);
    atomicAdd(&g_stat[C1 + c], ss);
    if (c == 0) atomicAdd(&g_cnt, (float)cnt);
}

// ---------------- finalize BN ----------------
__global__ void fin1_kernel(const float* __restrict__ g1, const float* __restrict__ be1) {
    int c = threadIdx.x;
    float cnt  = fmaxf(g_cnt, 1.f);
    float mean = g_stat[c] / cnt;
    float var  = g_stat[C1 + c] / cnt - mean * mean;
    float sc   = g1[c] * rsqrtf(var + EPSV);
    g_scale1[c] = sc;
    g_shift1[c] = be1[c] - mean * sc;
}
__global__ void fin2_kernel(const float* __restrict__ g2, const float* __restrict__ be2) {
    int c = threadIdx.x;
    float cnt  = fmaxf(g_cnt, 1.f);
    float mean = g_stat[256 + c] / cnt;
    float var  = g_stat[512 + c] / cnt - mean * mean;
    float sc   = g2[c] * rsqrtf(var + EPSV);
    g_scale2[c] = sc;
    g_shift2[c] = be2[c] - mean * sc;
}

// ================ f16 mma.sync m16n8k16 GEMM, 4-stage cp.async, BK=32 =========
// CTA 128x128 tile, 4 warps (2m x 2n), warp tile 64x64. Stage = 32 k-halfs.
// ONE __syncthreads per epoch (post-wait sync also orders buffer reuse).
// GRID: x = n-tile (fastest), y = row tile (A dup L2-absorbed).
// MODE 2: A=g_h1 (K=128), BN1+ReLU fp32 at frag, bias=b2, mask -> g_h + poolmax
// MODE 3: A=g_h  (K=256), identity, bias=pbias -> g_h2 + stats
// MODE 4: A=g_h2 (K=256), BN2+ReLU fp32 at frag, bias=b4, mask -> final max only
#define PAD32 40       // halfs per row (32 + 8); 20-word stride, conflict-free
#define STAGE_BYTES 10240   // 128 * 40 * 2
#define NSTG  4
#define DYN_TOTAL (NSTG * STAGE_BYTES * 2)   // 81920

template <int KDIM, int NDIM, int MODE>
__global__ __launch_bounds__(128, 2) void mma_gemm(const half* __restrict__ Wg,
                                                   const float* __restrict__ biasv,
                                                   const int* __restrict__ mask) {
    constexpr bool BNACT  = (MODE != 3);
    constexpr bool STOREO = (MODE != 4);
    constexpr bool POOLE  = (MODE != 3);
    constexpr bool STATS  = (MODE == 3);
    constexpr int  NKB    = KDIM / 32;
    constexpr int  SCSZ   = BNACT ? KDIM : 1;

    const half* A   = (MODE == 2) ? g_h1 : (MODE == 3) ? g_h : g_h2;
    half*       Out = (MODE == 2) ? g_h  : g_h2;

    extern __shared__ char dyn[];
    __shared__ float sBias[128];
    __shared__ float sScale[SCSZ];
    __shared__ float sShift[SCSZ];
    __shared__ uint32_t sPool[128];
    __shared__ float sS[128], sSS[128];

    const int t = threadIdx.x;
    const int rowBase = blockIdx.y * 128;   // row tile on y
    const int nBase   = blockIdx.x * 128;   // n tile on x (fastest)
    const int batch   = rowBase >> 9;

    if (t < 128) { sPool[t] = 0u; sS[t] = 0.f; sSS[t] = 0.f; }
    if (MODE == 3) {
        if (t < 128) sBias[t] = g_pbias[batch * C2 + nBase + t];
    } else {
        if (t < 128) sBias[t] = biasv[nBase + t];
        const float* sc = (MODE == 2) ? g_scale1 : g_scale2;
        const float* sh = (MODE == 2) ? g_shift1 : g_shift2;
        for (int r = t; r < KDIM; r += 128) { sScale[r] = sc[r]; sShift[r] = sh[r]; }
    }

    const int w  = t >> 5, l = t & 31;
    const int g  = l >> 2, c = l & 3;
    const int wm = w & 1, wn = w >> 1;
    const int mrow0 = wm * 64;
    const int ncol0 = wn * 64;

    uint32_t asm_base[NSTG], bsm_base[NSTG];
#pragma unroll
    for (int s = 0; s < NSTG; s++) {
        asm_base[s] = smem_u32(dyn + s * STAGE_BYTES);
        bsm_base[s] = smem_u32(dyn + NSTG * STAGE_BYTES + s * STAGE_BYTES);
    }

    const half* aG = A + (size_t)rowBase * KDIM;
    const half* bG = Wg + (size_t)nBase * KDIM;

    // Per stage: 128 rows x 32 halfs = 64B/row = 512 x 16B chunks; 4/thread each A,B
    auto issue_tile = [&](int kb, int buf) {
#pragma unroll
        for (int i = 0; i < 4; i++) {
            int f = i * 128 + t;
            int r = f >> 2, hc = f & 3;
            cp_async16_cg(asm_base[buf] + (uint32_t)r * 80 + (uint32_t)hc * 16,
                          aG + (size_t)r * KDIM + kb * 32 + hc * 8);
        }
#pragma unroll
        for (int i = 0; i < 4; i++) {
            int f = i * 128 + t;
            int n = f >> 2, hc = f & 3;
            cp_async16_ca(bsm_base[buf] + (uint32_t)n * 80 + (uint32_t)hc * 16,
                          bG + (size_t)n * KDIM + kb * 32 + hc * 8);
        }
        CP_COMMIT();
    };

    float acc[4][8][4];
#pragma unroll
    for (int mt = 0; mt < 4; mt++)
#pragma unroll
        for (int nt = 0; nt < 8; nt++)
#pragma unroll
            for (int q = 0; q < 4; q++) acc[mt][nt][q] = 0.f;

    issue_tile(0, 0);
    if (NKB > 1) issue_tile(1, 1);
    if (NKB > 2) issue_tile(2, 2);

#pragma unroll 1
    for (int kb = 0; kb < NKB; kb++) {
        const int buf = kb % NSTG;
        // groups still in flight after the one we need: min(2, NKB-1-kb)
        if (kb + 2 < NKB)      { CP_WAIT2(); }
        else if (kb + 1 < NKB) { CP_WAIT1(); }
        else                   { CP_WAIT0(); }
        __syncthreads();   // single barrier: data-ready + buffer-reuse ordering
        if (kb + 3 < NKB) issue_tile(kb + 3, (kb + 3) % NSTG);

        const half* AsBuf = (const half*)(dyn + buf * STAGE_BYTES);
        const half* BsBuf = (const half*)(dyn + NSTG * STAGE_BYTES + buf * STAGE_BYTES);

#pragma unroll
        for (int ks = 0; ks < 2; ks++) {
            float s0 = 1.f, s1 = 1.f, s2 = 1.f, s3 = 1.f;
            float h0 = 0.f, h1v = 0.f, h2v = 0.f, h3 = 0.f;
            if (BNACT) {
                int k0 = kb * 32 + ks * 16 + 2 * c;
                s0 = sScale[k0];     h0  = sShift[k0];
                s1 = sScale[k0 + 1]; h1v = sShift[k0 + 1];
                s2 = sScale[k0 + 8]; h2v = sShift[k0 + 8];
                s3 = sScale[k0 + 9]; h3  = sShift[k0 + 9];
            }

            uint32_t afr[4][4];
#pragma unroll
            for (int mt = 0; mt < 4; mt++) {
                const half* ap = &AsBuf[(mrow0 + mt * 16 + g) * PAD32 + ks * 16];
                uint32_t w0 = *(const uint32_t*)(ap + 2 * c);
                uint32_t w1 = *(const uint32_t*)(ap + 8 * PAD32 + 2 * c);
                uint32_t w2 = *(const uint32_t*)(ap + 2 * c + 8);
                uint32_t w3 = *(const uint32_t*)(ap + 8 * PAD32 + 2 * c + 8);
                if (BNACT) {
                    float2 u0 = uph2(w0), u1 = uph2(w1), u2 = uph2(w2), u3 = uph2(w3);
                    u0.x = fmaxf(fmaf(u0.x, s0, h0), 0.f);  u0.y = fmaxf(fmaf(u0.y, s1, h1v), 0.f);
                    u1.x = fmaxf(fmaf(u1.x, s0, h0), 0.f);  u1.y = fmaxf(fmaf(u1.y, s1, h1v), 0.f);
                    u2.x = fmaxf(fmaf(u2.x, s2, h2v), 0.f); u2.y = fmaxf(fmaf(u2.y, s3, h3), 0.f);
                    u3.x = fmaxf(fmaf(u3.x, s2, h2v), 0.f); u3.y = fmaxf(fmaf(u3.y, s3, h3), 0.f);
                    w0 = packh2(u0.x, u0.y);
                    w1 = packh2(u1.x, u1.y);
                    w2 = packh2(u2.x, u2.y);
                    w3 = packh2(u3.x, u3.y);
                }
                afr[mt][0] = w0; afr[mt][1] = w1; afr[mt][2] = w2; afr[mt][3] = w3;
            }
#pragma unroll
            for (int nt = 0; nt < 8; nt++) {
                const half* bp = &BsBuf[(ncol0 + nt * 8 + g) * PAD32 + ks * 16];
                uint32_t b0 = *(const uint32_t*)(bp + 2 * c);
                uint32_t b1 = *(const uint32_t*)(bp + 2 * c + 8);
#pragma unroll
                for (int mt = 0; mt < 4; mt++) {
                    asm volatile(
                        "mma.sync.aligned.m16n8k16.row.col.f32.f16.f16.f32 "
                        "{%0,%1,%2,%3}, {%4,%5,%6,%7}, {%8,%9}, {%0,%1,%2,%3};"
                        : "+f"(acc[mt][nt][0]), "+f"(acc[mt][nt][1]),
                          "+f"(acc[mt][nt][2]), "+f"(acc[mt][nt][3])
                        : "r"(afr[mt][0]), "r"(afr[mt][1]),
                          "r"(afr[mt][2]), "r"(afr[mt][3]),
                          "r"(b0), "r"(b1));
                }
            }
        }
        // no end-of-body sync: next iteration's post-wait sync orders reuse
    }
    __syncthreads();   // protect epilogue smem reductions vs last compute

    // ---- epilogue: f16 store + fused reductions ----
    float lmax[8][2];
    float stS[8][2], stSS[8][2];
    if (POOLE) {
#pragma unroll
        for (int nt = 0; nt < 8; nt++) { lmax[nt][0] = -3.4e38f; lmax[nt][1] = -3.4e38f; }
    }
    if (STATS) {
#pragma unroll
        for (int nt = 0; nt < 8; nt++) {
            stS[nt][0] = 0.f; stS[nt][1] = 0.f; stSS[nt][0] = 0.f; stSS[nt][1] = 0.f;
        }
    }

#pragma unroll
    for (int mt = 0; mt < 4; mt++) {
        int r0 = rowBase + mrow0 + mt * 16 + g;
        int r1 = r0 + 8;
        float m0 = MASK_AT(mask, r0) ? 1.f : 0.f;
        float m1 = MASK_AT(mask, r1) ? 1.f : 0.f;
        half* o0 = Out + (size_t)r0 * NDIM + nBase;
        half* o1 = Out + (size_t)r1 * NDIM + nBase;
#pragma unroll
        for (int nt = 0; nt < 8; nt++) {
            int col = ncol0 + nt * 8 + 2 * c;
            float bx = sBias[col], by = sBias[col + 1];
            float ux = acc[mt][nt][0] + bx, uy = acc[mt][nt][1] + by;
            float vx = acc[mt][nt][2] + bx, vy = acc[mt][nt][3] + by;
            if (MODE != 3) { ux *= m0; uy *= m0; vx *= m1; vy *= m1; }
            if (STOREO) {
                *(uint32_t*)(o0 + col) = packh2(ux, uy);
                *(uint32_t*)(o1 + col) = packh2(vx, vy);
            }
            if (POOLE) {
                lmax[nt][0] = fmaxf(lmax[nt][0], fmaxf(ux, vx));
                lmax[nt][1] = fmaxf(lmax[nt][1], fmaxf(uy, vy));
            }
            if (STATS) {
                stS[nt][0]  += m0 * ux + m1 * vx;
                stS[nt][1]  += m0 * uy + m1 * vy;
                stSS[nt][0] += m0 * ux * ux + m1 * vx * vx;
                stSS[nt][1] += m0 * uy * uy + m1 * vy * vy;
            }
        }
    }

    if (POOLE) {
#pragma unroll
        for (int nt = 0; nt < 8; nt++) {
            atomicMax(&sPool[ncol0 + nt * 8 + 2 * c],     fenc(lmax[nt][0]));
            atomicMax(&sPool[ncol0 + nt * 8 + 2 * c + 1], fenc(lmax[nt][1]));
        }
    }
    if (STATS) {
#pragma unroll
        for (int nt = 0; nt < 8; nt++) {
            int col = ncol0 + nt * 8 + 2 * c;
            atomicAdd(&sS[col],      stS[nt][0]);
            atomicAdd(&sS[col + 1],  stS[nt][1]);
            atomicAdd(&sSS[col],     stSS[nt][0]);
            atomicAdd(&sSS[col + 1], stSS[nt][1]);
        }
    }
    __syncthreads();
    if (t < 128) {
        if (MODE == 2) atomicMax(&g_poolenc[batch * C2 + nBase + t], sPool[t]);
        if (MODE == 4) atomicMax(&g_outenc[batch * ENC + t], sPool[t]);
        if (STATS) {
            atomicAdd(&g_stat[256 + nBase + t], sS[t]);
            atomicAdd(&g_stat[512 + nBase + t], sSS[t]);
        }
    }
}

// ---------------- pbias = pooled @ W3[256:512] + b3 ----------------
__global__ void pbias_kernel(const float* __restrict__ W3, const float* __restrict__ b3) {
    __shared__ float sp[C2];
    int b = blockIdx.x, c = threadIdx.x;  // 256
    sp[c] = fdec(g_poolenc[b * C2 + c]);
    __syncthreads();
    float v = b3[c];
    for (int k = 0; k < C2; k++) v = fmaf(sp[k], W3[(size_t)(C2 + k) * C2 + c], v);
    g_pbias[b * C2 + c] = v;
}

// ---------------- decode final output ----------------
__global__ void decode_out_kernel(float* __restrict__ out) {
    int i = blockIdx.x * 256 + threadIdx.x;
    if (i < BB * ENC) out[i] = fdec(g_outenc[i]);
}

// ---------------- launch ----------------
extern "C" void kernel_launch(void* const* d_in, const int* in_sizes, int n_in,
                              void* d_out, int out_size) {
    const float* x  = (const float*)d_in[0];
    const int*   mk = (const int*)d_in[1];
    const float* W1 = (const float*)d_in[2];
    const float* b1 = (const float*)d_in[3];
    const float* g1 = (const float*)d_in[4];
    const float* be1= (const float*)d_in[5];
    const float* W2 = (const float*)d_in[6];
    const float* b2 = (const float*)d_in[7];
    const float* W3 = (const float*)d_in[8];
    const float* b3 = (const float*)d_in[9];
    const float* g2 = (const float*)d_in[10];
    const float* be2= (const float*)d_in[11];
    const float* W4 = (const float*)d_in[12];
    const float* b4 = (const float*)d_in[13];
    float* out = (float*)d_out;

    half *w2t, *w3t, *w4t;
    cudaGetSymbolAddress((void**)&w2t, g_w2t);
    cudaGetSymbolAddress((void**)&w3t, g_w3t);
    cudaGetSymbolAddress((void**)&w4t, g_w4t);

    static bool attr_done = false;
    if (!attr_done) {
        cudaFuncSetAttribute(mma_gemm<128, 256, 2>, cudaFuncAttributeMaxDynamicSharedMemorySize, DYN_TOTAL);
        cudaFuncSetAttribute(mma_gemm<256, 256, 3>, cudaFuncAttributeMaxDynamicSharedMemorySize, DYN_TOTAL);
        cudaFuncSetAttribute(mma_gemm<256, 128, 4>, cudaFuncAttributeMaxDynamicSharedMemorySize, DYN_TOTAL);
        attr_done = true;
    }

    init_kernel<<<(BB * C2 + 255) / 256, 256>>>();
    wcvt_t_kernel<<<(C1 * C2 + 255) / 256, 256>>>(W2, w2t, C1, C2);
    wcvt_t_kernel<<<(C2 * C2 + 255) / 256, 256>>>(W3, w3t, C2, C2);  // rows 0..255 of W3
    wcvt_t_kernel<<<(C2 * ENC + 255) / 256, 256>>>(W4, w4t, C2, ENC);

    k1_kernel<<<MTOT / 32, 128>>>(x, mk, W1, b1);
    fin1_kernel<<<1, 128>>>(g1, be1);

    // grid: x = n-tiles (fastest), y = row tiles -> n-halves co-resident, A L2-absorbed
    mma_gemm<128, 256, 2><<<dim3(2, MTOT / 128), 128, DYN_TOTAL>>>(w2t, b2, mk);
    pbias_kernel<<<BB, 256>>>(W3, b3);
    mma_gemm<256, 256, 3><<<dim3(2, MTOT / 128), 128, DYN_TOTAL>>>(w3t, nullptr, mk);
    fin2_kernel<<<1, 256>>>(g2, be2);
    mma_gemm<256, 128, 4><<<dim3(1, MTOT / 128), 128, DYN_TOTAL>>>(w4t, b4, mk);
    decode_out_kernel<<<(BB * ENC + 255) / 256, 256>>>(out);
}

// round 17
// speedup vs baseline: 1.6616x; 1.0438x over previous
#include <cuda_runtime.h>
#include <cuda_fp16.h>
#include <cstdint>

// Problem dims
#define BB   512
#define NN   512
#define MTOT (BB*NN)      // 262144 rows
#define C1   128
#define C2   256
#define ENC  128
#define EPSV 1e-5f

#define MASK_AT(mk, i) ((mk)[i] != 0)

// ---------------- scratch (activations in f16) ----------------
__device__ half g_h1[(size_t)MTOT * C1];    // h1 pre-BN [BN,128]
__device__ half g_h [(size_t)MTOT * C2];    // masked h  [BN,256]
__device__ half g_h2[(size_t)MTOT * C2];    // h2 (incl pbias) [BN,256]
__device__ float g_pbias[BB * C2];
__device__ float g_stat[768];
__device__ float g_cnt;
__device__ uint32_t g_poolenc[BB * C2];
__device__ uint32_t g_outenc [BB * ENC];
// f16 weights, transposed [n][k]
__device__ half g_w2t[C2 * C1];
__device__ half g_w3t[C2 * C2];
__device__ half g_w4t[ENC * C2];

__device__ __forceinline__ uint32_t smem_u32(const void* p) {
    uint32_t a;
    asm("{ .reg .u64 t; cvta.to.shared.u64 t, %1; cvt.u32.u64 %0, t; }" : "=r"(a) : "l"(p));
    return a;
}
__device__ __forceinline__ void cp_async16_cg(uint32_t dst, const void* src) {
    asm volatile("cp.async.cg.shared.global [%0], [%1], 16;" :: "r"(dst), "l"(src));
}
__device__ __forceinline__ void cp_async16_ca(uint32_t dst, const void* src) {
    asm volatile("cp.async.ca.shared.global [%0], [%1], 16;" :: "r"(dst), "l"(src));
}
#define CP_COMMIT() asm volatile("cp.async.commit_group;" ::: "memory")
#define CP_WAIT0()  asm volatile("cp.async.wait_group 0;" ::: "memory")
#define CP_WAIT1()  asm volatile("cp.async.wait_group 1;" ::: "memory")
#define CP_WAIT2()  asm volatile("cp.async.wait_group 2;" ::: "memory")

__device__ __forceinline__ uint32_t fenc(float f) {
    uint32_t u = __float_as_uint(f);
    return (u >> 31) ? ~u : (u | 0x80000000u);
}
__device__ __forceinline__ float fdec(uint32_t e) {
    return __uint_as_float((e >> 31) ? (e ^ 0x80000000u) : ~e);
}
__device__ __forceinline__ uint32_t packh2(float x, float y) {
    uint32_t r;
    asm("cvt.rn.f16x2.f32 %0, %1, %2;" : "=r"(r) : "f"(y), "f"(x));
    return r;
}
__device__ __forceinline__ float2 uph2(uint32_t u) {
    half2 h = *(half2*)&u;
    return __half22float2(h);
}

// ---------------- prologue: init + all weight transposes, one kernel ----------------
// work items: [0, 131072) init poolenc/outenc/stat/cnt; then weight cvts by range.
__global__ void prologue_kernel(const float* __restrict__ W2,
                                const float* __restrict__ W3,
                                const float* __restrict__ W4) {
    int i = blockIdx.x * 256 + threadIdx.x;
    // init section
    if (i < 768) g_stat[i] = 0.f;
    if (i == 768) g_cnt = 0.f;
    if (i < BB * C2) g_poolenc[i] = 0u;
    if (i < BB * ENC) g_outenc[i] = 0u;
    // weight transposes: w2t (32768), w3t (65536), w4t (32768)
    if (i < C2 * C1) {                      // w2t[n][k] from W2[k][n], K=C1,N=C2
        int n = i / C1, k = i % C1;
        g_w2t[i] = __float2half_rn(W2[(size_t)k * C2 + n]);
    }
    if (i < C2 * C2) {                      // w3t from W3 rows 0..255
        int n = i / C2, k = i % C2;
        g_w3t[i] = __float2half_rn(W3[(size_t)k * C2 + n]);
    }
    if (i < ENC * C2) {                     // w4t from W4, K=C2,N=ENC
        int n = i / C2, k = i % C2;
        g_w4t[i] = __float2half_rn(W4[(size_t)k * ENC + n]);
    }
}

// ---------------- K1: h1 = x@W1 + b1 (f16), masked BN1 stats; 128 rows/block ----------------
__global__ __launch_bounds__(128) void k1_kernel(const float* __restrict__ x,
                                                 const int* __restrict__ mask,
                                                 const float* __restrict__ W1,
                                                 const float* __restrict__ b1) {
    __shared__ float sW[6 * C1];
    __shared__ float sb[C1];
    int c = threadIdx.x;
#pragma unroll
    for (int k = 0; k < 6; k++) sW[k * C1 + c] = W1[k * C1 + c];
    sb[c] = b1[c];
    __syncthreads();

    int row0 = blockIdx.x * 128;
    float s = 0.f, ss = 0.f;
    int cnt = 0;
#pragma unroll 4
    for (int r = 0; r < 128; r++) {
        int row = row0 + r;
        const float* xr = x + (size_t)row * 6;
        float v = sb[c];
#pragma unroll
        for (int k = 0; k < 6; k++) v = fmaf(xr[k], sW[k * C1 + c], v);
        g_h1[(size_t)row * C1 + c] = __float2half_rn(v);
        if (MASK_AT(mask, row)) { s += v; ss += v * v; cnt++; }
    }
    atomicAdd(&g_stat[c],      s);
    atomicAdd(&g_stat[C1 + c], ss);
    if (c == 0) atomicAdd(&g_cnt, (float)cnt);
}

// ================ f16 mma.sync m16n8k16 GEMM, 4-stage cp.async, BK=32 =========
// BN finalize done per-CTA from g_stat (fin kernels removed).
#define PAD32 40
#define STAGE_BYTES 10240   // 128 * 40 * 2
#define NSTG  4
#define DYN_TOTAL (NSTG * STAGE_BYTES * 2)   // 81920

template <int KDIM, int NDIM, int MODE>
__global__ __launch_bounds__(128, 2) void mma_gemm(const half* __restrict__ Wg,
                                                   const float* __restrict__ biasv,
                                                   const float* __restrict__ gamv,
                                                   const float* __restrict__ betv,
                                                   const int* __restrict__ mask) {
    constexpr bool BNACT  = (MODE != 3);
    constexpr bool STOREO = (MODE != 4);
    constexpr bool POOLE  = (MODE != 3);
    constexpr bool STATS  = (MODE == 3);
    constexpr int  NKB    = KDIM / 32;
    constexpr int  SCSZ   = BNACT ? KDIM : 1;
    constexpr int  STATOFF = (MODE == 2) ? 0 : 256;   // stat base for BN

    const half* A   = (MODE == 2) ? g_h1 : (MODE == 3) ? g_h : g_h2;
    half*       Out = (MODE == 2) ? g_h  : g_h2;

    extern __shared__ char dyn[];
    __shared__ float sBias[128];
    __shared__ float sScale[SCSZ];
    __shared__ float sShift[SCSZ];
    __shared__ uint32_t sPool[128];
    __shared__ float sS[128], sSS[128];

    const int t = threadIdx.x;
    const int rowBase = blockIdx.y * 128;   // row tile on y
    const int nBase   = blockIdx.x * 128;   // n tile on x (fastest)
    const int batch   = rowBase >> 9;

    if (t < 128) { sPool[t] = 0u; sS[t] = 0.f; sSS[t] = 0.f; }
    if (MODE == 3) {
        if (t < 128) sBias[t] = g_pbias[batch * C2 + nBase + t];
    } else {
        if (t < 128) sBias[t] = biasv[nBase + t];
        // finalize BN per-CTA from accumulated stats
        float cnt = fmaxf(g_cnt, 1.f);
        for (int r = t; r < KDIM; r += 128) {
            float mean = g_stat[STATOFF + r] / cnt;
            float var  = g_stat[STATOFF + (MODE == 2 ? C1 : C2) + r] / cnt - mean * mean;
            float sc   = gamv[r] * rsqrtf(var + EPSV);
            sScale[r] = sc;
            sShift[r] = betv[r] - mean * sc;
        }
    }

    const int w  = t >> 5, l = t & 31;
    const int g  = l >> 2, c = l & 3;
    const int wm = w & 1, wn = w >> 1;
    const int mrow0 = wm * 64;
    const int ncol0 = wn * 64;

    uint32_t asm_base[NSTG], bsm_base[NSTG];
#pragma unroll
    for (int s = 0; s < NSTG; s++) {
        asm_base[s] = smem_u32(dyn + s * STAGE_BYTES);
        bsm_base[s] = smem_u32(dyn + NSTG * STAGE_BYTES + s * STAGE_BYTES);
    }

    const half* aG = A + (size_t)rowBase * KDIM;
    const half* bG = Wg + (size_t)nBase * KDIM;

    auto issue_tile = [&](int kb, int buf) {
#pragma unroll
        for (int i = 0; i < 4; i++) {
            int f = i * 128 + t;
            int r = f >> 2, hc = f & 3;
            cp_async16_cg(asm_base[buf] + (uint32_t)r * 80 + (uint32_t)hc * 16,
                          aG + (size_t)r * KDIM + kb * 32 + hc * 8);
        }
#pragma unroll
        for (int i = 0; i < 4; i++) {
            int f = i * 128 + t;
            int n = f >> 2, hc = f & 3;
            cp_async16_ca(bsm_base[buf] + (uint32_t)n * 80 + (uint32_t)hc * 16,
                          bG + (size_t)n * KDIM + kb * 32 + hc * 8);
        }
        CP_COMMIT();
    };

    float acc[4][8][4];
#pragma unroll
    for (int mt = 0; mt < 4; mt++)
#pragma unroll
        for (int nt = 0; nt < 8; nt++)
#pragma unroll
            for (int q = 0; q < 4; q++) acc[mt][nt][q] = 0.f;

    issue_tile(0, 0);
    if (NKB > 1) issue_tile(1, 1);
    if (NKB > 2) issue_tile(2, 2);

#pragma unroll 1
    for (int kb = 0; kb < NKB; kb++) {
        const int buf = kb % NSTG;
        if (kb + 2 < NKB)      { CP_WAIT2(); }
        else if (kb + 1 < NKB) { CP_WAIT1(); }
        else                   { CP_WAIT0(); }
        __syncthreads();   // single barrier: data-ready + buffer-reuse ordering
        if (kb + 3 < NKB) issue_tile(kb + 3, (kb + 3) % NSTG);

        const half* AsBuf = (const half*)(dyn + buf * STAGE_BYTES);
        const half* BsBuf = (const half*)(dyn + NSTG * STAGE_BYTES + buf * STAGE_BYTES);

#pragma unroll
        for (int ks = 0; ks < 2; ks++) {
            float s0 = 1.f, s1 = 1.f, s2 = 1.f, s3 = 1.f;
            float h0 = 0.f, h1v = 0.f, h2v = 0.f, h3 = 0.f;
            if (BNACT) {
                int k0 = kb * 32 + ks * 16 + 2 * c;
                s0 = sScale[k0];     h0  = sShift[k0];
                s1 = sScale[k0 + 1]; h1v = sShift[k0 + 1];
                s2 = sScale[k0 + 8]; h2v = sShift[k0 + 8];
                s3 = sScale[k0 + 9]; h3  = sShift[k0 + 9];
            }

            uint32_t afr[4][4];
#pragma unroll
            for (int mt = 0; mt < 4; mt++) {
                const half* ap = &AsBuf[(mrow0 + mt * 16 + g) * PAD32 + ks * 16];
                uint32_t w0 = *(const uint32_t*)(ap + 2 * c);
                uint32_t w1 = *(const uint32_t*)(ap + 8 * PAD32 + 2 * c);
                uint32_t w2 = *(const uint32_t*)(ap + 2 * c + 8);
                uint32_t w3 = *(const uint32_t*)(ap + 8 * PAD32 + 2 * c + 8);
                if (BNACT) {
                    float2 u0 = uph2(w0), u1 = uph2(w1), u2 = uph2(w2), u3 = uph2(w3);
                    u0.x = fmaxf(fmaf(u0.x, s0, h0), 0.f);  u0.y = fmaxf(fmaf(u0.y, s1, h1v), 0.f);
                    u1.x = fmaxf(fmaf(u1.x, s0, h0), 0.f);  u1.y = fmaxf(fmaf(u1.y, s1, h1v), 0.f);
                    u2.x = fmaxf(fmaf(u2.x, s2, h2v), 0.f); u2.y = fmaxf(fmaf(u2.y, s3, h3), 0.f);
                    u3.x = fmaxf(fmaf(u3.x, s2, h2v), 0.f); u3.y = fmaxf(fmaf(u3.y, s3, h3), 0.f);
                    w0 = packh2(u0.x, u0.y);
                    w1 = packh2(u1.x, u1.y);
                    w2 = packh2(u2.x, u2.y);
                    w3 = packh2(u3.x, u3.y);
                }
                afr[mt][0] = w0; afr[mt][1] = w1; afr[mt][2] = w2; afr[mt][3] = w3;
            }
#pragma unroll
            for (int nt = 0; nt < 8; nt++) {
                const half* bp = &BsBuf[(ncol0 + nt * 8 + g) * PAD32 + ks * 16];
                uint32_t b0 = *(const uint32_t*)(bp + 2 * c);
                uint32_t b1 = *(const uint32_t*)(bp + 2 * c + 8);
#pragma unroll
                for (int mt = 0; mt < 4; mt++) {
                    asm volatile(
                        "mma.sync.aligned.m16n8k16.row.col.f32.f16.f16.f32 "
                        "{%0,%1,%2,%3}, {%4,%5,%6,%7}, {%8,%9}, {%0,%1,%2,%3};"
                        : "+f"(acc[mt][nt][0]), "+f"(acc[mt][nt][1]),
                          "+f"(acc[mt][nt][2]), "+f"(acc[mt][nt][3])
                        : "r"(afr[mt][0]), "r"(afr[mt][1]),
                          "r"(afr[mt][2]), "r"(afr[mt][3]),
                          "r"(b0), "r"(b1));
                }
            }
        }
    }
    __syncthreads();   // protect epilogue smem reductions vs last compute

    // ---- epilogue: f16 store + fused reductions ----
    float lmax[8][2];
    float stS[8][2], stSS[8][2];
    if (POOLE) {
#pragma unroll
        for (int nt = 0; nt < 8; nt++) { lmax[nt][0] = -3.4e38f; lmax[nt][1] = -3.4e38f; }
    }
    if (STATS) {
#pragma unroll
        for (int nt = 0; nt < 8; nt++) {
            stS[nt][0] = 0.f; stS[nt][1] = 0.f; stSS[nt][0] = 0.f; stSS[nt][1] = 0.f;
        }
    }

#pragma unroll
    for (int mt = 0; mt < 4; mt++) {
        int r0 = rowBase + mrow0 + mt * 16 + g;
        int r1 = r0 + 8;
        float m0 = MASK_AT(mask, r0) ? 1.f : 0.f;
        float m1 = MASK_AT(mask, r1) ? 1.f : 0.f;
        half* o0 = Out + (size_t)r0 * NDIM + nBase;
        half* o1 = Out + (size_t)r1 * NDIM + nBase;
#pragma unroll
        for (int nt = 0; nt < 8; nt++) {
            int col = ncol0 + nt * 8 + 2 * c;
            float bx = sBias[col], by = sBias[col + 1];
            float ux = acc[mt][nt][0] + bx, uy = acc[mt][nt][1] + by;
            float vx = acc[mt][nt][2] + bx, vy = acc[mt][nt][3] + by;
            if (MODE != 3) { ux *= m0; uy *= m0; vx *= m1; vy *= m1; }
            if (STOREO) {
                *(uint32_t*)(o0 + col) = packh2(ux, uy);
                *(uint32_t*)(o1 + col) = packh2(vx, vy);
            }
            if (POOLE) {
                lmax[nt][0] = fmaxf(lmax[nt][0], fmaxf(ux, vx));
                lmax[nt][1] = fmaxf(lmax[nt][1], fmaxf(uy, vy));
            }
            if (STATS) {
                stS[nt][0]  += m0 * ux + m1 * vx;
                stS[nt][1]  += m0 * uy + m1 * vy;
                stSS[nt][0] += m0 * ux * ux + m1 * vx * vx;
                stSS[nt][1] += m0 * uy * uy + m1 * vy * vy;
            }
        }
    }

    if (POOLE) {
#pragma unroll
        for (int nt = 0; nt < 8; nt++) {
            atomicMax(&sPool[ncol0 + nt * 8 + 2 * c],     fenc(lmax[nt][0]));
            atomicMax(&sPool[ncol0 + nt * 8 + 2 * c + 1], fenc(lmax[nt][1]));
        }
    }
    if (STATS) {
#pragma unroll
        for (int nt = 0; nt < 8; nt++) {
            int col = ncol0 + nt * 8 + 2 * c;
            atomicAdd(&sS[col],      stS[nt][0]);
            atomicAdd(&sS[col + 1],  stS[nt][1]);
            atomicAdd(&sSS[col],     stSS[nt][0]);
            atomicAdd(&sSS[col + 1], stSS[nt][1]);
        }
    }
    __syncthreads();
    if (t < 128) {
        if (MODE == 2) atomicMax(&g_poolenc[batch * C2 + nBase + t], sPool[t]);
        if (MODE == 4) atomicMax(&g_outenc[batch * ENC + t], sPool[t]);
        if (STATS) {
            atomicAdd(&g_stat[256 + nBase + t], sS[t]);
            atomicAdd(&g_stat[512 + nBase + t], sSS[t]);
        }
    }
}

// ---------------- pbias = pooled @ W3[256:512] + b3 ----------------
__global__ void pbias_kernel(const float* __restrict__ W3, const float* __restrict__ b3) {
    __shared__ float sp[C2];
    int b = blockIdx.x, c = threadIdx.x;  // 256
    sp[c] = fdec(g_poolenc[b * C2 + c]);
    __syncthreads();
    float v = b3[c];
    for (int k = 0; k < C2; k++) v = fmaf(sp[k], W3[(size_t)(C2 + k) * C2 + c], v);
    g_pbias[b * C2 + c] = v;
}

// ---------------- decode final output ----------------
__global__ void decode_out_kernel(float* __restrict__ out) {
    int i = blockIdx.x * 256 + threadIdx.x;
    if (i < BB * ENC) out[i] = fdec(g_outenc[i]);
}

// ---------------- launch ----------------
extern "C" void kernel_launch(void* const* d_in, const int* in_sizes, int n_in,
                              void* d_out, int out_size) {
    const float* x  = (const float*)d_in[0];
    const int*   mk = (const int*)d_in[1];
    const float* W1 = (const float*)d_in[2];
    const float* b1 = (const float*)d_in[3];
    const float* g1 = (const float*)d_in[4];
    const float* be1= (const float*)d_in[5];
    const float* W2 = (const float*)d_in[6];
    const float* b2 = (const float*)d_in[7];
    const float* W3 = (const float*)d_in[8];
    const float* b3 = (const float*)d_in[9];
    const float* g2 = (const float*)d_in[10];
    const float* be2= (const float*)d_in[11];
    const float* W4 = (const float*)d_in[12];
    const float* b4 = (const float*)d_in[13];
    float* out = (float*)d_out;

    half *w2t, *w3t, *w4t;
    cudaGetSymbolAddress((void**)&w2t, g_w2t);
    cudaGetSymbolAddress((void**)&w3t, g_w3t);
    cudaGetSymbolAddress((void**)&w4t, g_w4t);

    static bool attr_done = false;
    if (!attr_done) {
        cudaFuncSetAttribute(mma_gemm<128, 256, 2>, cudaFuncAttributeMaxDynamicSharedMemorySize, DYN_TOTAL);
        cudaFuncSetAttribute(mma_gemm<256, 256, 3>, cudaFuncAttributeMaxDynamicSharedMemorySize, DYN_TOTAL);
        cudaFuncSetAttribute(mma_gemm<256, 128, 4>, cudaFuncAttributeMaxDynamicSharedMemorySize, DYN_TOTAL);
        attr_done = true;
    }

    prologue_kernel<<<(C2 * C2 + 255) / 256, 256>>>(W2, W3, W4);
    k1_kernel<<<MTOT / 128, 128>>>(x, mk, W1, b1);

    // grid: x = n-tiles (fastest), y = row tiles -> n-halves co-resident, A L2-absorbed
    mma_gemm<128, 256, 2><<<dim3(2, MTOT / 128), 128, DYN_TOTAL>>>(w2t, b2, g1, be1, mk);
    pbias_kernel<<<BB, 256>>>(W3, b3);
    mma_gemm<256, 256, 3><<<dim3(2, MTOT / 128), 128, DYN_TOTAL>>>(w3t, nullptr, nullptr, nullptr, mk);
    mma_gemm<256, 128, 4><<<dim3(1, MTOT / 128), 128, DYN_TOTAL>>>(w4t, b4, g2, be2, mk);
    decode_out_kernel<<<(BB * ENC + 255) / 256, 256>>>(out);
}